// round 14
// baseline (speedup 1.0000x reference)
#include <cuda_runtime.h>

#define BB   256
#define SS   1024
#define HH   512
#define CC   10
#define GROUPS 16
#define CPG  8           // CTAs per group
#define BPG  16          // batch rows per group
#define JPC  64          // j rows per CTA
#define THREADS 512
#define XCHUNK 64
#define HPAD 516         // padded h_s row stride (floats)
#define RPAD 64          // red row stride (floats)
#define WROW 130         // w2k row stride in floats (65 float2 = 520B)
#define WPH_LD 516

// shared memory layout (float offsets)
#define OFF_W    0                              // w2k [256 kp][130] = 33280 f
#define OFF_H    (256 * WROW)                   // h_s [16][516] = 8256 f
#define OFF_RED  (OFF_H + BPG * HPAD)           // red [8][16][64] = 8192 f
#define OFF_WPH  (OFF_RED + 8 * BPG * RPAD)     // wph [10][516] = 5160 f
#define OFF_X    (OFF_WPH + CC * WPH_LD)        // x_s [16][64] = 1024 f
#define OFF_WX   (OFF_X + BPG * XCHUNK)
#define OFF_BH   (OFF_WX + 64)
#define OFF_BP   (OFF_BH + 64)
#define SMEM_FLOATS (OFF_BP + 16)
#define SMEM_BYTES  (SMEM_FLOATS * 4)           // 224,224 B

__device__ float    g_h[2][BB * HH];        // double-buffered hidden state (1 MB)
__device__ unsigned g_bar[GROUPS * 32];     // per-group barrier counters

__device__ __forceinline__ float2 ffma2(float2 a, float2 b, float2 c)
{
    float2 d;
    asm("{\n\t"
        ".reg .b64 A,Bq,Cq;\n\t"
        "mov.b64 A, {%2,%3};\n\t"
        "mov.b64 Bq, {%4,%5};\n\t"
        "mov.b64 Cq, {%6,%7};\n\t"
        "fma.rn.f32x2 Cq, A, Bq, Cq;\n\t"
        "mov.b64 {%0,%1}, Cq;\n\t"
        "}"
        : "=f"(d.x), "=f"(d.y)
        : "f"(a.x), "f"(a.y), "f"(b.x), "f"(b.y), "f"(c.x), "f"(c.y));
    return d;
}

__device__ __forceinline__ void bar_release_add(unsigned* p)
{
    asm volatile("red.release.gpu.global.add.u32 [%0], 1;" :: "l"(p) : "memory");
}
__device__ __forceinline__ unsigned bar_acquire_ld(const unsigned* p)
{
    unsigned v;
    asm volatile("ld.acquire.gpu.global.u32 %0, [%1];" : "=r"(v) : "l"(p) : "memory");
    return v;
}

__global__ void zero_bar_kernel()
{
    for (int i = threadIdx.x; i < GROUPS * 32; i += blockDim.x) g_bar[i] = 0u;
}

__global__ void __launch_bounds__(THREADS, 1)
rnn_kernel(const float* __restrict__ x,    const float* __restrict__ w_hx,
           const float* __restrict__ w_hh, const float* __restrict__ w_ph,
           const float* __restrict__ b_h,  const float* __restrict__ b_p,
           float* __restrict__ out)
{
    extern __shared__ float sm[];
    float*  w2f  = sm + OFF_W;      // [kp][130] : float2 w2k[kp][65]
    float*  h_s  = sm + OFF_H;      // [16][HPAD]
    float*  red  = sm + OFF_RED;    // [8 kw][16 b][RPAD]
    float*  wph  = sm + OFF_WPH;
    float*  x_s  = sm + OFF_X;      // [16][64]
    float*  wx_s = sm + OFF_WX;
    float*  bh_s = sm + OFF_BH;
    float*  bp_s = sm + OFF_BP;

    const int tid = threadIdx.x;
    const int grp = blockIdx.x / CPG;
    const int cta = blockIdx.x % CPG;
    const int j0  = cta * JPC;
    const int b0  = grp * BPG;

    // ---------------- one-time staging ----------------
    for (int i = tid; i < JPC * HH; i += THREADS) {          // w_hh slice -> k-pair major
        int j = i >> 9, k = i & (HH - 1);
        w2f[(k >> 1) * WROW + j * 2 + (k & 1)] = w_hh[(j0 + j) * HH + k];
    }
    for (int i = tid; i < CC * HH; i += THREADS) {
        int c = i >> 9, j = i & (HH - 1);
        wph[c * WPH_LD + j] = w_ph[i];
    }
    if (tid < JPC) { wx_s[tid] = w_hx[j0 + tid]; bh_s[tid] = b_h[j0 + tid]; }
    if (tid < CC)  { bp_s[tid] = b_p[tid]; }
    for (int i = tid; i < BPG * HPAD; i += THREADS) h_s[i] = 0.f;   // h0 = 0
    __syncthreads();

    const int wid  = tid >> 5;
    const int lane = tid & 31;
    const int kw   = wid & 7;       // k-eighth (team)
    const int bhf  = wid >> 3;      // b-half: rows [bhf*8, bhf*8+8)

    unsigned* bar = &g_bar[grp * 32];
    const float2* w2k = (const float2*)w2f;   // index kp*65 + j

    for (int t = 0; t < SS; ++t) {
        // ---- stage x chunk every 64 steps ----
        if ((t & (XCHUNK - 1)) == 0) {
            for (int i = tid; i < BPG * XCHUNK; i += THREADS) {
                int bb = i >> 6, tt = i & 63;
                x_s[i] = x[(b0 + bb) * SS + t + tt];
            }
            __syncthreads();
        }

        // ---- GEMM: warp covers 8b x 64j over its 64 k ----
        float2 accA[8], accB[8];
        #pragma unroll
        for (int b = 0; b < 8; ++b) { accA[b] = make_float2(0.f, 0.f); accB[b] = make_float2(0.f, 0.f); }
        {
            const int k4beg = kw * 16;           // 16 k4 per team (4k per k4)
            const float* hbase = h_s + bhf * 8 * HPAD;
            #pragma unroll 2
            for (int k4 = k4beg; k4 < k4beg + 16; ++k4) {
                float2 wA0 = w2k[(2 * k4 + 0) * 65 + lane];
                float2 wB0 = w2k[(2 * k4 + 0) * 65 + lane + 32];
                float2 wA1 = w2k[(2 * k4 + 1) * 65 + lane];
                float2 wB1 = w2k[(2 * k4 + 1) * 65 + lane + 32];
                const float* hp = hbase + (k4 << 2);
                #pragma unroll
                for (int b = 0; b < 8; ++b) {
                    float4 hq = *(const float4*)(hp + b * HPAD);   // uniform broadcast
                    float2 h01 = make_float2(hq.x, hq.y);
                    float2 h23 = make_float2(hq.z, hq.w);
                    accA[b] = ffma2(h01, wA0, accA[b]);
                    accA[b] = ffma2(h23, wA1, accA[b]);
                    accB[b] = ffma2(h01, wB0, accB[b]);
                    accB[b] = ffma2(h23, wB1, accB[b]);
                }
            }
        }

        // ---- store k-partials ----
        #pragma unroll
        for (int b = 0; b < 8; ++b) {
            const int row = kw * BPG + bhf * 8 + b;
            red[row * RPAD + lane]      = accA[b].x + accA[b].y;
            red[row * RPAD + lane + 32] = accB[b].x + accB[b].y;
        }
        __syncthreads();

        // ---- final reduce (+bias +x*wx) + tanh + publish to L2 ----
        const int p1 = (t + 1) & 1;
        float* gdst = &g_h[p1][b0 * HH + j0];
        #pragma unroll
        for (int i = 0; i < 2; ++i) {
            int o = tid + i * THREADS;           // 1024 outputs: 16b x 64j
            int b = o >> 6, j = o & 63;
            const float* rp = red + b * RPAD + j;
            float s01 = rp[0 * BPG * RPAD] + rp[1 * BPG * RPAD];
            float s23 = rp[2 * BPG * RPAD] + rp[3 * BPG * RPAD];
            float s45 = rp[4 * BPG * RPAD] + rp[5 * BPG * RPAD];
            float s67 = rp[6 * BPG * RPAD] + rp[7 * BPG * RPAD];
            float s = (s01 + s23) + (s45 + s67)
                    + fmaf(x_s[b * XCHUNK + (t & 63)], wx_s[j], bh_s[j]);
            s = fminf(fmaxf(s, -15.f), 15.f);
            float e  = __expf(2.f * s);
            float hn = __fdividef(e - 1.f, e + 1.f);
            __stcg(&gdst[b * HH + j], hn);
        }

        // ---- group barrier: sync + release-red + acquire-spin ----
        __syncthreads();
        if (tid == 0) {
            bar_release_add(bar);
            const unsigned tgt = (unsigned)(CPG * (t + 1));
            while (bar_acquire_ld(bar) < tgt) __nanosleep(16);
        }
        __syncthreads();

        // ---- reload full h_{t+1} (16 x 512 = 2048 float4) from L2 ----
        {
            const float4* src = (const float4*)&g_h[p1][b0 * HH];
            float4*       dst = (float4*)h_s;
            #pragma unroll
            for (int i = 0; i < 4; ++i) {                    // 4 x 512 = 2048 float4
                int idx = tid + i * THREADS;
                int b = idx >> 7, c4 = idx & 127;
                dst[b * (HPAD / 4) + c4] = __ldcg(src + idx);
            }
        }
        __syncthreads();

        // ---- projection: warps 0/1 only, shuffle reduce, no block sync ----
        if (wid < 2) {
            const int row = cta * 2 + wid;
            const float4* hrow = (const float4*)(h_s + row * HPAD);
            float4 hv[4];
            #pragma unroll
            for (int q = 0; q < 4; ++q) hv[q] = hrow[lane + q * 32];
            float s[CC];
            #pragma unroll
            for (int c = 0; c < CC; ++c) {
                const float4* wrow = (const float4*)(wph + c * WPH_LD);
                float a0 = 0.f, a1 = 0.f;
                #pragma unroll
                for (int q = 0; q < 4; ++q) {
                    float4 wv = wrow[lane + q * 32];
                    a0 = fmaf(hv[q].x, wv.x, a0); a1 = fmaf(hv[q].y, wv.y, a1);
                    a0 = fmaf(hv[q].z, wv.z, a0); a1 = fmaf(hv[q].w, wv.w, a1);
                }
                s[c] = a0 + a1;
                #pragma unroll
                for (int off = 16; off > 0; off >>= 1)
                    s[c] += __shfl_xor_sync(0xffffffffu, s[c], off);
            }
            if (lane == 0) {
                float* op = out + ((size_t)(b0 + row) * SS + t) * CC;
                #pragma unroll
                for (int c = 0; c < CC; ++c) op[c] = s[c] + bp_s[c];
            }
        }
    }
}

extern "C" void kernel_launch(void* const* d_in, const int* in_sizes, int n_in,
                              void* d_out, int out_size)
{
    const float* xx   = (const float*)d_in[0];
    const float* w_hx = (const float*)d_in[1];
    const float* w_hh = (const float*)d_in[2];
    const float* w_ph = (const float*)d_in[3];
    const float* b_h  = (const float*)d_in[4];
    const float* b_p  = (const float*)d_in[5];
    float* out = (float*)d_out;

    cudaFuncSetAttribute(rnn_kernel,
                         cudaFuncAttributeMaxDynamicSharedMemorySize, SMEM_BYTES);
    zero_bar_kernel<<<1, 256>>>();
    rnn_kernel<<<GROUPS * CPG, THREADS, SMEM_BYTES>>>(xx, w_hx, w_hh, w_ph, b_h, b_p, out);
}

// round 16
// speedup vs baseline: 1.0122x; 1.0122x over previous
#include <cuda_runtime.h>

#define BB   256
#define SS   1024
#define HH   512
#define CC   10
#define GROUPS 16
#define CPG  8           // CTAs per group
#define BPG  16          // batch rows per group
#define JPC  64          // j rows per CTA
#define THREADS 256
#define NWARP 8
#define XCHUNK 64
#define HPAD 516         // padded h_s row stride (floats)
#define RPAD 64          // red row stride (floats)
#define WROW 130         // w2k row stride in floats (65 float2 = 520B)
#define WPO_LD 68        // own w_ph slice row stride

// shared memory layout (float offsets)
#define OFF_W    0                              // w2k [256 kp][130] = 33280 f
#define OFF_H    (256 * WROW)                   // h_s [16][516] = 8256 f
#define OFF_RED  (OFF_H + BPG * HPAD)           // red [8][16][64] = 8192 f
#define OFF_X    (OFF_RED + NWARP * BPG * RPAD) // x_s [16][64] = 1024 f
#define OFF_WPO  (OFF_X + BPG * XCHUNK)         // wpo [10][68] = 680 f
#define OFF_WX   (OFF_WPO + CC * WPO_LD)
#define OFF_BH   (OFF_WX + 64)
#define OFF_BP   (OFF_BH + 64)
#define SMEM_FLOATS (OFF_BP + 16)
#define SMEM_BYTES  (SMEM_FLOATS * 4)           // ~206.3 KB

__device__ float    g_h[2][BB * HH];            // double-buffered hidden state (1 MB)
__device__ unsigned g_flag[GROUPS * CPG * 32];  // per-CTA step flags, 128B apart

__device__ __forceinline__ float2 ffma2(float2 a, float2 b, float2 c)
{
    float2 d;
    asm("{\n\t"
        ".reg .b64 A,Bq,Cq;\n\t"
        "mov.b64 A, {%2,%3};\n\t"
        "mov.b64 Bq, {%4,%5};\n\t"
        "mov.b64 Cq, {%6,%7};\n\t"
        "fma.rn.f32x2 Cq, A, Bq, Cq;\n\t"
        "mov.b64 {%0,%1}, Cq;\n\t"
        "}"
        : "=f"(d.x), "=f"(d.y)
        : "f"(a.x), "f"(a.y), "f"(b.x), "f"(b.y), "f"(c.x), "f"(c.y));
    return d;
}

__device__ __forceinline__ void flag_release_store(unsigned* p, unsigned v)
{
    asm volatile("st.release.gpu.global.u32 [%0], %1;" :: "l"(p), "r"(v) : "memory");
}
__device__ __forceinline__ unsigned flag_acquire_ld(const unsigned* p)
{
    unsigned v;
    asm volatile("ld.acquire.gpu.global.u32 %0, [%1];" : "=r"(v) : "l"(p) : "memory");
    return v;
}

__global__ void zero_flag_kernel()
{
    for (int i = threadIdx.x; i < GROUPS * CPG * 32; i += blockDim.x) g_flag[i] = 0u;
}

__global__ void __launch_bounds__(THREADS, 1)
rnn_kernel(const float* __restrict__ x,    const float* __restrict__ w_hx,
           const float* __restrict__ w_hh, const float* __restrict__ w_ph,
           const float* __restrict__ b_h,  const float* __restrict__ b_p,
           float* __restrict__ out)
{
    extern __shared__ float sm[];
    float*  w2f  = sm + OFF_W;      // [kp][130] : float2 w2k[kp][65]
    float*  h_s  = sm + OFF_H;      // [16][HPAD]
    float*  red  = sm + OFF_RED;    // [8 kw][16 b][RPAD]
    float*  x_s  = sm + OFF_X;      // [16][64]
    float*  wpo  = sm + OFF_WPO;    // own w_ph slice [10][WPO_LD]
    float*  wx_s = sm + OFF_WX;
    float*  bh_s = sm + OFF_BH;
    float*  bp_s = sm + OFF_BP;

    const int tid = threadIdx.x;
    const int grp = blockIdx.x / CPG;
    const int cta = blockIdx.x % CPG;
    const int j0  = cta * JPC;
    const int b0  = grp * BPG;

    // ---------------- one-time staging ----------------
    for (int i = tid; i < JPC * HH; i += THREADS) {          // w_hh slice -> k-pair major
        int j = i >> 9, k = i & (HH - 1);
        w2f[(k >> 1) * WROW + j * 2 + (k & 1)] = w_hh[(j0 + j) * HH + k];
    }
    for (int i = tid; i < CC * JPC; i += THREADS) {          // own w_ph slice
        int c = i >> 6, j = i & 63;
        wpo[c * WPO_LD + j] = w_ph[c * HH + j0 + j];
    }
    if (tid < JPC) { wx_s[tid] = w_hx[j0 + tid]; bh_s[tid] = b_h[j0 + tid]; }
    if (tid < CC)  { bp_s[tid] = b_p[tid]; }
    for (int i = tid; i < BPG * HPAD; i += THREADS) h_s[i] = 0.f;   // h0 = 0
    __syncthreads();

    const int wid  = tid >> 5;      // warp == k-team; source CTA == wid
    const int lane = tid & 31;
    const int kw   = wid;

    unsigned* myflag = &g_flag[(grp * CPG + cta) * 32];
    const unsigned* srcflag = &g_flag[(grp * CPG + kw) * 32];
    const float2* w2k = (const float2*)w2f;   // index kp*65 + j

    for (int t = 0; t < SS; ++t) {
        // ---- stage x chunk every 64 steps ----
        if ((t & (XCHUNK - 1)) == 0) {
            for (int i = tid; i < BPG * XCHUNK; i += THREADS) {
                int bb = i >> 6, tt = i & 63;
                x_s[i] = x[(b0 + bb) * SS + t + tt];
            }
            __syncthreads();
        }

        // ---- k-eighth GEMM: warp covers 16b x 64j over its 64 k ----
        float2 accA[16], accB[16];
        #pragma unroll
        for (int b = 0; b < 16; ++b) { accA[b] = make_float2(0.f, 0.f); accB[b] = make_float2(0.f, 0.f); }
        {
            const int k4beg = kw * 16;           // 16 k4 per team (4k per k4)
            #pragma unroll 2
            for (int k4 = k4beg; k4 < k4beg + 16; ++k4) {
                float2 wA0 = w2k[(2 * k4 + 0) * 65 + lane];
                float2 wB0 = w2k[(2 * k4 + 0) * 65 + lane + 32];
                float2 wA1 = w2k[(2 * k4 + 1) * 65 + lane];
                float2 wB1 = w2k[(2 * k4 + 1) * 65 + lane + 32];
                const float* hp = h_s + (k4 << 2);
                #pragma unroll
                for (int b = 0; b < 16; ++b) {
                    float4 hq = *(const float4*)(hp + b * HPAD);   // uniform broadcast
                    float2 h01 = make_float2(hq.x, hq.y);
                    float2 h23 = make_float2(hq.z, hq.w);
                    accA[b] = ffma2(h01, wA0, accA[b]);
                    accA[b] = ffma2(h23, wA1, accA[b]);
                    accB[b] = ffma2(h01, wB0, accB[b]);
                    accB[b] = ffma2(h23, wB1, accB[b]);
                }
            }
        }

        // ---- store k-partials ----
        #pragma unroll
        for (int b = 0; b < 16; ++b) {
            red[(kw * BPG + b) * RPAD + lane]      = accA[b].x + accA[b].y;
            red[(kw * BPG + b) * RPAD + lane + 32] = accB[b].x + accB[b].y;
        }
        __syncthreads();    // sync1: partials visible

        // ---- final reduce (+bias +x*wx) + tanh ----
        // publish to L2 (for peers) AND into h_s own columns (for own team + projection)
        const int p1 = (t + 1) & 1;
        float* gdst = &g_h[p1][b0 * HH + j0];
        #pragma unroll
        for (int i = 0; i < 4; ++i) {
            int o = tid + i * THREADS;           // 1024 outputs: 16b x 64j
            int b = o >> 6, j = o & 63;
            const float* rp = red + b * RPAD + j;
            float s01 = rp[0 * BPG * RPAD] + rp[1 * BPG * RPAD];
            float s23 = rp[2 * BPG * RPAD] + rp[3 * BPG * RPAD];
            float s45 = rp[4 * BPG * RPAD] + rp[5 * BPG * RPAD];
            float s67 = rp[6 * BPG * RPAD] + rp[7 * BPG * RPAD];
            float s = (s01 + s23) + (s45 + s67)
                    + fmaf(x_s[b * XCHUNK + (t & 63)], wx_s[j], bh_s[j]);
            s = fminf(fmaxf(s, -15.f), 15.f);
            float e  = __expf(2.f * s);
            float hn = __fdividef(e - 1.f, e + 1.f);
            __stcg(&gdst[b * HH + j], hn);
            h_s[b * HPAD + j0 + j] = hn;         // own slice direct to smem
        }
        __syncthreads();    // sync2: h_s own cols + publishes done; red reusable
        if (tid == 0) flag_release_store(myflag, (unsigned)(t + 1));

        // ---- projection partials from own 64 columns (covers flag latency) ----
        {
            const int row = wid * 2 + (lane >> 4);      // 2 rows per warp
            const int j4  = lane & 15;
            float4 hv = *(const float4*)(h_s + row * HPAD + j0 + j4 * 4);
            float* op = out + ((size_t)(b0 + row) * SS + t) * CC;
            #pragma unroll
            for (int c = 0; c < CC; ++c) {
                float4 wv = *(const float4*)(wpo + c * WPO_LD + j4 * 4);
                float p = fmaf(hv.x, wv.x, fmaf(hv.y, wv.y, fmaf(hv.z, wv.z, hv.w * wv.w)));
                #pragma unroll
                for (int off = 8; off > 0; off >>= 1)
                    p += __shfl_down_sync(0xffffffffu, p, off, 16);
                if (j4 == 0) {
                    float add = (cta == 0) ? p + bp_s[c] : p;
                    atomicAdd(op + c, add);
                }
            }
        }

        // ---- per-team slice exchange (own team already has its columns) ----
        if (kw != cta && t + 1 < SS) {
            if (lane == 0) {
                while (flag_acquire_ld(srcflag) < (unsigned)(t + 1)) __nanosleep(20);
            }
            __syncwarp();
            const float* gsrc = &g_h[p1][b0 * HH + kw * 64];
            const int r  = lane >> 4;            // row parity
            const int c4 = lane & 15;            // float4 within 64-col slice
            #pragma unroll
            for (int i = 0; i < 8; ++i) {
                int row = 2 * i + r;
                float4 v = __ldcg((const float4*)(gsrc + row * HH) + c4);
                *((float4*)(h_s + row * HPAD + kw * 64) + c4) = v;
            }
            __syncwarp();
        }
    }
}

extern "C" void kernel_launch(void* const* d_in, const int* in_sizes, int n_in,
                              void* d_out, int out_size)
{
    const float* xx   = (const float*)d_in[0];
    const float* w_hx = (const float*)d_in[1];
    const float* w_hh = (const float*)d_in[2];
    const float* w_ph = (const float*)d_in[3];
    const float* b_h  = (const float*)d_in[4];
    const float* b_p  = (const float*)d_in[5];
    float* out = (float*)d_out;

    cudaFuncSetAttribute(rnn_kernel,
                         cudaFuncAttributeMaxDynamicSharedMemorySize, SMEM_BYTES);
    cudaMemsetAsync(out, 0, (size_t)out_size * sizeof(float));
    zero_flag_kernel<<<1, 256>>>();
    rnn_kernel<<<GROUPS * CPG, THREADS, SMEM_BYTES>>>(xx, w_hx, w_hh, w_ph, b_h, b_p, out);
}